// round 8
// baseline (speedup 1.0000x reference)
#include <cuda_runtime.h>
#include <math.h>
#include <stdint.h>

#define MBATCH 16384
#define DDIM   256
#define NELEM  (MBATCH * DDIM)

constexpr float HG = 0.005f;   // gamma / 2

constexpr int BM = 128, BN = 256, BK = 64;
constexpr int ASTRIDE = 68;    // 68 % 32 == 4 -> conflict-free direct frag lds
constexpr int ABUF = BM * ASTRIDE;
constexpr int SMEM_BYTES = 2 * ABUF * (int)sizeof(float);   // 69632
constexpr int NTHREADS = 512;  // 16 warps: 4m x 4n, warp tile 32x64

enum { MODE_SP = 0, MODE_GV = 1, MODE_ZC = 2, MODE_FXZ = 3, MODE_FXV = 4, MODE_RW = 5 };

// ---------------- scratch (static device arrays; no runtime alloc) --------
__device__ float gSZ [NELEM];
__device__ float gE  [NELEM];
__device__ float gR  [NELEM];
__device__ float gHGR[NELEM];
__device__ float gBUF[NELEM];
__device__ float gV  [NELEM];
__device__ float gVH0[NELEM];
__device__ float gVH1[NELEM];
__device__ float gTMP[NELEM];
__device__ float gZP0[NELEM];
__device__ float gZP1[NELEM];
__device__ float gZP2[NELEM];

// Precomputed tf32 W fragments (mma-fragment order), 256KB each.
// idx = ((kt*32 + nt)*32 + lane)*2 + reg ; n = nt*8+(lane>>2), k = kt*8+(lane&3)+4*reg
__device__ uint32_t gWN[65536];   // B[k][n] = W[k][n]   (A @ W)
__device__ uint32_t gWT[65536];   // B[k][n] = W[n][k]   (A @ W^T)

// ---------------- math helpers --------------------------------------------
__device__ __forceinline__ float sp_f(float x) {          // precise softplus
    return fmaxf(x, 0.0f) + log1pf(expf(-fabsf(x)));
}
__device__ __forceinline__ float sp_fast(float x) {       // MUFU softplus
    return fmaxf(x, 0.0f) + __logf(1.0f + __expf(-fabsf(x)));
}
__device__ __forceinline__ float4 ld4(const float* p) { return *(const float4*)p; }

__device__ __forceinline__ uint32_t to_tf32(float f) {
    uint32_t r;
    asm("cvt.rna.tf32.f32 %0, %1;" : "=r"(r) : "f"(f));
    return r;
}
__device__ __forceinline__ void mma_tf32(float c[4], const uint32_t a[4], const uint32_t b[2]) {
    asm volatile(
        "mma.sync.aligned.m16n8k8.row.col.f32.tf32.tf32.f32 "
        "{%0,%1,%2,%3}, {%4,%5,%6,%7}, {%8,%9}, {%0,%1,%2,%3};"
        : "+f"(c[0]), "+f"(c[1]), "+f"(c[2]), "+f"(c[3])
        : "r"(a[0]), "r"(a[1]), "r"(a[2]), "r"(a[3]), "r"(b[0]), "r"(b[1]));
}
__device__ __forceinline__ void cp16(float* smem_dst, const float* gsrc) {
    uint32_t s = (uint32_t)__cvta_generic_to_shared(smem_dst);
    asm volatile("cp.async.cg.shared.global [%0], [%1], 16;" :: "r"(s), "l"(gsrc));
}
__device__ __forceinline__ void cp_commit() { asm volatile("cp.async.commit_group;"); }
template <int N>
__device__ __forceinline__ void cp_wait() { asm volatile("cp.async.wait_group %0;" :: "n"(N)); }

// ---------------- W fragment precompute -------------------------------------
__global__ void prep_wfrags(const float* __restrict__ W) {
    int idx = blockIdx.x * 256 + threadIdx.x;   // 0..65535
    int reg  = idx & 1;
    int lane = (idx >> 1) & 31;
    int nt   = (idx >> 6) & 31;
    int kt   = idx >> 11;
    int n = nt * 8 + (lane >> 2);
    int k = kt * 8 + (lane & 3) + 4 * reg;
    gWN[idx] = to_tf32(W[k * DDIM + n]);
    gWT[idx] = to_tf32(W[n * DDIM + k]);
}

// ---------------- fused epilogue (per float2) -------------------------------
template <int MODE>
__device__ __forceinline__ void epi2(int off, int c, float a0, float a1,
                                     const float* __restrict__ bias,
                                     const float* __restrict__ X1,
                                     const float* __restrict__ X2,
                                     const float* __restrict__ X3,
                                     const float* __restrict__ X4,
                                     float* __restrict__ O1, float* __restrict__ O2,
                                     float* __restrict__ O3)
{
    if (MODE == MODE_SP) {
        float2 b = *(const float2*)(bias + c);
        float s0 = sp_f(a0 + b.x), s1 = sp_f(a1 + b.y);
        float e0 = 0.5f * expm1f(-s0), e1 = 0.5f * expm1f(-s1);
        *(float2*)(O1 + off) = make_float2(s0, s1);
        *(float2*)(O2 + off) = make_float2(e0, e1);
        *(float2*)(O3 + off) = make_float2(__fdividef(e0, s0), __fdividef(e1, s1));
    } else if (MODE == MODE_GV) {
        float2 b = *(const float2*)(bias + c);
        float s0 = sp_f(a0 + b.x), s1 = sp_f(a1 + b.y);
        *(float2*)(O1 + off) = make_float2(__fdividef(0.5f * expm1f(-s0), s0),
                                           __fdividef(0.5f * expm1f(-s1), s1));
    } else if (MODE == MODE_ZC) {
        float2 z = *(const float2*)(X1 + off);
        float2 s = *(const float2*)(X2 + off);
        float2 v = *(const float2*)(X3 + off);
        float svh0 = s.x * v.x, svh1 = s.y * v.y;
        float2 bf = make_float2(HG * (svh0 + 2.0f * a0), HG * (svh1 + 2.0f * a1));
        float2 zn = make_float2(z.x + bf.x + HG * svh0, z.y + bf.y + HG * svh1);
        *(float2*)(O1 + off) = bf;
        *(float2*)(O2 + off) = zn;
    } else if (MODE == MODE_FXZ) {
        float2 b  = *(const float2*)(bias + c);
        float2 zn = *(const float2*)(X1 + off);
        float2 bf = *(const float2*)(X2 + off);
        float2 v  = *(const float2*)(X3 + off);
        float s0 = sp_fast(a0 + b.x), s1 = sp_fast(a1 + b.y);
        *(float2*)(O1 + off) = make_float2(zn.x + bf.x + HG * s0 * v.x,
                                           zn.y + bf.y + HG * s1 * v.y);
    } else if (MODE == MODE_FXV) {
        float2 vb  = *(const float2*)(X3 + off);
        float2 hgr = *(const float2*)(X4 + off);
        *(float2*)(O1 + off) = make_float2(vb.x - hgr.x + HG * a0,
                                           vb.y - hgr.y + HG * a1);
    } else {  // MODE_RW
        *(float2*)(O1 + off) = make_float2(HG * a0, HG * a1);
    }
}

// ---------------- one fused GEMM op (CTA-wide, BM x BN = 128 x 256) ---------
template <int MODE, bool TRANSB>
__device__ __forceinline__ void gemm_op(
    float* __restrict__ Asm, int row0, int tid,
    const float* __restrict__ A, const float* __restrict__ bias,
    const float* __restrict__ X1, const float* __restrict__ X2,
    const float* __restrict__ X3, const float* __restrict__ X4,
    float* __restrict__ O1, float* __restrict__ O2, float* __restrict__ O3)
{
    const uint32_t* __restrict__ Wf = TRANSB ? gWT : gWN;
    const int lane   = tid & 31;
    const int wid    = tid >> 5;
    const int warp_m = wid >> 2;   // 0..3, 32 rows each
    const int warp_n = wid & 3;    // 0..3, 64 cols each

    // visibility of previous op's global outputs + smem WAR protection
    __syncthreads();

    float acc[2][8][4];
#pragma unroll
    for (int i = 0; i < 2; i++)
#pragma unroll
        for (int j = 0; j < 8; j++)
#pragma unroll
            for (int q = 0; q < 4; q++) acc[i][j][q] = 0.0f;

    auto copyA = [&](int buf, int c) {
#pragma unroll
        for (int i = 0; i < 4; i++) {
            const int idx = i * NTHREADS + tid;    // 0..2047
            const int m   = idx >> 4;              // 0..127
            const int o   = (idx & 15) * 4;        // 0..60
            const int g   = (row0 + m) * DDIM + c * BK + o;
            float* dst = Asm + buf * ABUF + m * ASTRIDE + o;
            if (MODE == MODE_FXV) {
                float4 e4 = ld4(X1 + g);
                float4 v4 = ld4(X2 + g);
                float4 av;
                av.x = e4.x * v4.x * v4.x;
                av.y = e4.y * v4.y * v4.y;
                av.z = e4.z * v4.z * v4.z;
                av.w = e4.w * v4.w * v4.w;
                *(float4*)dst = av;
            } else {
                cp16(dst, A + g);
            }
        }
    };

    copyA(0, 0);
    cp_commit();

#pragma unroll 1
    for (int c = 0; c < 4; c++) {
        if (c < 3) { copyA((c + 1) & 1, c + 1); cp_commit(); cp_wait<1>(); }
        else       { cp_wait<0>(); }
        __syncthreads();

        const float* Ab = Asm + (c & 1) * ABUF;
#pragma unroll 4
        for (int ktl = 0; ktl < 8; ktl++) {
            const int kt = c * 8 + ktl;
            uint32_t bf[8][2];
#pragma unroll
            for (int nt = 0; nt < 8; nt++) {
                const int ntg = warp_n * 8 + nt;
                uint2 v = __ldg((const uint2*)(Wf + ((kt * 32 + ntg) * 32 + lane) * 2));
                bf[nt][0] = v.x; bf[nt][1] = v.y;
            }
            const int kk = ktl * 8 + (lane & 3);
#pragma unroll
            for (int mt = 0; mt < 2; mt++) {
                const int r = warp_m * 32 + mt * 16 + (lane >> 2);
                uint32_t af[4];
                af[0] = __float_as_uint(Ab[r * ASTRIDE + kk]);
                af[1] = __float_as_uint(Ab[(r + 8) * ASTRIDE + kk]);
                af[2] = __float_as_uint(Ab[r * ASTRIDE + kk + 4]);
                af[3] = __float_as_uint(Ab[(r + 8) * ASTRIDE + kk + 4]);
#pragma unroll
                for (int nt = 0; nt < 8; nt++)
                    mma_tf32(acc[mt][nt], af, bf[nt]);
            }
        }
        __syncthreads();
    }

    // ---- fused epilogue ----
#pragma unroll
    for (int mt = 0; mt < 2; mt++) {
#pragma unroll
        for (int nt = 0; nt < 8; nt++) {
            const int r = row0 + warp_m * 32 + mt * 16 + (lane >> 2);
            const int c = warp_n * 64 + nt * 8 + ((lane & 3) << 1);
            const int off0 = r * DDIM + c;
            const int off1 = off0 + 8 * DDIM;
            epi2<MODE>(off0, c, acc[mt][nt][0], acc[mt][nt][1], bias, X1, X2, X3, X4, O1, O2, O3);
            epi2<MODE>(off1, c, acc[mt][nt][2], acc[mt][nt][3], bias, X1, X2, X3, X4, O1, O2, O3);
        }
    }
}

// ---------------- persistent megakernel -------------------------------------
__global__ __launch_bounds__(NTHREADS, 1)
void rhmc_mega(const float* __restrict__ z0, const float* __restrict__ v0,
               const float* __restrict__ bias, float* __restrict__ out)
{
    extern __shared__ float Asm[];
    const int row0 = blockIdx.x * BM;
    const int tid  = threadIdx.x;

    const float* zcur = z0;
    const float* vcur = v0;

    // s, e, r of z0 ; HGR = HG * (r @ W^T)
    gemm_op<MODE_SP, false>(Asm, row0, tid, zcur, bias, 0, 0, 0, 0, gSZ, gE, gR);
    gemm_op<MODE_RW, true >(Asm, row0, tid, gR,   bias, 0, 0, 0, 0, gHGR, 0, 0);

    int cur = -1;
#pragma unroll 1
    for (int l = 0; l < 6; l++) {
        const int a = (cur < 0) ? 0 : (cur + 1) % 3;
        const int b = (cur < 0) ? 1 : (cur + 2) % 3;
        float* ZPa = (a == 0) ? gZP0 : (a == 1) ? gZP1 : gZP2;
        float* ZPb = (b == 0) ? gZP0 : (b == 1) ? gZP1 : gZP2;

        // fx_v: 8 iterations  vh <- vh - HGR + HG*((e*vh^2) @ W^T)
        const float* vh = vcur;
#pragma unroll 1
        for (int i = 0; i < 8; i++) {
            float* vo = (i & 1) ? gVH1 : gVH0;
            gemm_op<MODE_FXV, true>(Asm, row0, tid, 0, bias, gE, vh, vh, gHGR, vo, 0, 0);
            vh = vo;
        }
        // vh == gVH1

        // Gv(vh)
        gemm_op<MODE_GV, false>(Asm, row0, tid, vh, bias, 0, 0, 0, 0, gTMP, 0, 0);
        // BUF, zn_1
        gemm_op<MODE_ZC, true >(Asm, row0, tid, gTMP, bias, zcur, gSZ, vh, 0, gBUF, ZPa, 0);

        // fx_z: 7 more iterations
        const float* zn = ZPa;
#pragma unroll 1
        for (int i = 0; i < 7; i++) {
            float* zo = (i & 1) ? ZPa : ZPb;
            gemm_op<MODE_FXZ, false>(Asm, row0, tid, zn, bias, zn, gBUF, vh, 0, zo, 0, 0);
            zn = zo;
        }
        // zn == ZPb

        // s,e,r,HGR of z_new ; v_new
        gemm_op<MODE_SP, false>(Asm, row0, tid, zn, bias, 0, 0, 0, 0, gSZ, gE, gR);
        gemm_op<MODE_RW, true >(Asm, row0, tid, gR, bias, 0, 0, 0, 0, gHGR, 0, 0);
        gemm_op<MODE_FXV, true>(Asm, row0, tid, 0, bias, gE, vh, vh, gHGR, gV, 0, 0);

        zcur = zn;
        vcur = gV;
        cur  = b;
    }

    // ---- write this CTA's slab to d_out ----
    __syncthreads();
    const int base = row0 * DDIM;
#pragma unroll 1
    for (int i = tid; i < BM * DDIM / 4; i += NTHREADS) {
        ((float4*)(out + base))[i]         = ((const float4*)(zcur + base))[i];
        ((float4*)(out + NELEM + base))[i] = ((const float4*)(vcur + base))[i];
    }
}

// ---------------- host driver ----------------------------------------------
extern "C" void kernel_launch(void* const* d_in, const int* in_sizes, int n_in,
                              void* d_out, int out_size)
{
    const float* z0   = (const float*)d_in[0];
    const float* v0   = (const float*)d_in[1];
    const float* W    = (const float*)d_in[2];
    const float* bias = (const float*)d_in[3];

    cudaFuncSetAttribute(rhmc_mega, cudaFuncAttributeMaxDynamicSharedMemorySize, SMEM_BYTES);

    prep_wfrags<<<256, 256>>>(W);
    rhmc_mega<<<MBATCH / BM, NTHREADS, SMEM_BYTES>>>(z0, v0, bias, (float*)d_out);
}

// round 9
// speedup vs baseline: 1.1724x; 1.1724x over previous
#include <cuda_runtime.h>
#include <math.h>
#include <stdint.h>

#define MBATCH 16384
#define DDIM   256
#define NELEM  (MBATCH * DDIM)

constexpr float HG = 0.005f;   // gamma / 2

constexpr int BM = 64, BN = 256, BK = 64;
constexpr int ASTRIDE = 68;    // 68 % 32 == 4 -> conflict-free direct frag lds
constexpr int ABUF = BM * ASTRIDE;
constexpr int SMEM_BYTES = 2 * ABUF * (int)sizeof(float);   // 34816
constexpr int NTHREADS = 256;  // 8 warps: 2m x 4n, warp tile 32x64

enum { MODE_SP = 0, MODE_GV = 1, MODE_ZC = 2, MODE_FXZ = 3, MODE_FXV = 4, MODE_RW = 5 };

// ---------------- scratch (static device arrays; no runtime alloc) --------
__device__ float gSZ [NELEM];
__device__ float gE  [NELEM];
__device__ float gR  [NELEM];
__device__ float gHGR[NELEM];
__device__ float gBUF[NELEM];
__device__ float gV  [NELEM];
__device__ float gVH0[NELEM];
__device__ float gVH1[NELEM];
__device__ float gTMP[NELEM];
__device__ float gZP0[NELEM];
__device__ float gZP1[NELEM];
__device__ float gZP2[NELEM];

// Precomputed tf32 W fragments (mma-fragment order), 256KB each.
// idx = ((kt*32 + nt)*32 + lane)*2 + reg ; n = nt*8+(lane>>2), k = kt*8+(lane&3)+4*reg
__device__ uint32_t gWN[65536];   // B[k][n] = W[k][n]   (A @ W)
__device__ uint32_t gWT[65536];   // B[k][n] = W[n][k]   (A @ W^T)

// ---------------- math helpers --------------------------------------------
__device__ __forceinline__ float sp_f(float x) {          // precise softplus
    return fmaxf(x, 0.0f) + log1pf(expf(-fabsf(x)));
}
__device__ __forceinline__ float sp_fast(float x) {       // MUFU softplus
    return fmaxf(x, 0.0f) + __logf(1.0f + __expf(-fabsf(x)));
}
__device__ __forceinline__ float4 ld4(const float* p) { return *(const float4*)p; }

__device__ __forceinline__ uint32_t to_tf32(float f) {
    uint32_t r;
    asm("cvt.rna.tf32.f32 %0, %1;" : "=r"(r) : "f"(f));
    return r;
}
__device__ __forceinline__ void mma_tf32(float c[4], const uint32_t a[4], const uint32_t b[2]) {
    asm volatile(
        "mma.sync.aligned.m16n8k8.row.col.f32.tf32.tf32.f32 "
        "{%0,%1,%2,%3}, {%4,%5,%6,%7}, {%8,%9}, {%0,%1,%2,%3};"
        : "+f"(c[0]), "+f"(c[1]), "+f"(c[2]), "+f"(c[3])
        : "r"(a[0]), "r"(a[1]), "r"(a[2]), "r"(a[3]), "r"(b[0]), "r"(b[1]));
}
__device__ __forceinline__ void cp16(float* smem_dst, const float* gsrc) {
    uint32_t s = (uint32_t)__cvta_generic_to_shared(smem_dst);
    asm volatile("cp.async.cg.shared.global [%0], [%1], 16;" :: "r"(s), "l"(gsrc));
}
__device__ __forceinline__ void cp_commit() { asm volatile("cp.async.commit_group;"); }
template <int N>
__device__ __forceinline__ void cp_wait() { asm volatile("cp.async.wait_group %0;" :: "n"(N)); }

// ---------------- W fragment precompute -------------------------------------
__global__ void prep_wfrags(const float* __restrict__ W) {
    int idx = blockIdx.x * 256 + threadIdx.x;   // 0..65535
    int reg  = idx & 1;
    int lane = (idx >> 1) & 31;
    int nt   = (idx >> 6) & 31;
    int kt   = idx >> 11;
    int n = nt * 8 + (lane >> 2);
    int k = kt * 8 + (lane & 3) + 4 * reg;
    gWN[idx] = to_tf32(W[k * DDIM + n]);
    gWT[idx] = to_tf32(W[n * DDIM + k]);
}

// ---------------- fused epilogue (per float2) -------------------------------
template <int MODE>
__device__ __forceinline__ void epi2(int off, int c, float a0, float a1,
                                     const float* __restrict__ bias,
                                     const float* __restrict__ X1,
                                     const float* __restrict__ X2,
                                     const float* __restrict__ X3,
                                     const float* __restrict__ X4,
                                     float* __restrict__ O1, float* __restrict__ O2,
                                     float* __restrict__ O3)
{
    if (MODE == MODE_SP) {
        float2 b = *(const float2*)(bias + c);
        float s0 = sp_f(a0 + b.x), s1 = sp_f(a1 + b.y);
        float e0 = 0.5f * expm1f(-s0), e1 = 0.5f * expm1f(-s1);
        *(float2*)(O1 + off) = make_float2(s0, s1);
        *(float2*)(O2 + off) = make_float2(e0, e1);
        *(float2*)(O3 + off) = make_float2(__fdividef(e0, s0), __fdividef(e1, s1));
    } else if (MODE == MODE_GV) {
        float2 b = *(const float2*)(bias + c);
        float s0 = sp_f(a0 + b.x), s1 = sp_f(a1 + b.y);
        *(float2*)(O1 + off) = make_float2(__fdividef(0.5f * expm1f(-s0), s0),
                                           __fdividef(0.5f * expm1f(-s1), s1));
    } else if (MODE == MODE_ZC) {
        float2 z = *(const float2*)(X1 + off);
        float2 s = *(const float2*)(X2 + off);
        float2 v = *(const float2*)(X3 + off);
        float svh0 = s.x * v.x, svh1 = s.y * v.y;
        float2 bf = make_float2(HG * (svh0 + 2.0f * a0), HG * (svh1 + 2.0f * a1));
        float2 zn = make_float2(z.x + bf.x + HG * svh0, z.y + bf.y + HG * svh1);
        *(float2*)(O1 + off) = bf;
        *(float2*)(O2 + off) = zn;
    } else if (MODE == MODE_FXZ) {
        float2 b  = *(const float2*)(bias + c);
        float2 zn = *(const float2*)(X1 + off);
        float2 bf = *(const float2*)(X2 + off);
        float2 v  = *(const float2*)(X3 + off);
        float s0 = sp_fast(a0 + b.x), s1 = sp_fast(a1 + b.y);
        *(float2*)(O1 + off) = make_float2(zn.x + bf.x + HG * s0 * v.x,
                                           zn.y + bf.y + HG * s1 * v.y);
    } else if (MODE == MODE_FXV) {
        float2 vb  = *(const float2*)(X3 + off);
        float2 hgr = *(const float2*)(X4 + off);
        *(float2*)(O1 + off) = make_float2(vb.x - hgr.x + HG * a0,
                                           vb.y - hgr.y + HG * a1);
    } else {  // MODE_RW
        *(float2*)(O1 + off) = make_float2(HG * a0, HG * a1);
    }
}

// ---------------- one fused GEMM op (CTA-wide, BM x BN = 64 x 256) ----------
template <int MODE, bool TRANSB>
__device__ __forceinline__ void gemm_op(
    float* __restrict__ Asm, int row0, int tid,
    const float* __restrict__ A, const float* __restrict__ bias,
    const float* __restrict__ X1, const float* __restrict__ X2,
    const float* __restrict__ X3, const float* __restrict__ X4,
    float* __restrict__ O1, float* __restrict__ O2, float* __restrict__ O3)
{
    const uint32_t* __restrict__ Wf = TRANSB ? gWT : gWN;
    const int lane   = tid & 31;
    const int wid    = tid >> 5;
    const int warp_m = wid >> 2;   // 0..1, 32 rows each
    const int warp_n = wid & 3;    // 0..3, 64 cols each

    // visibility of previous op's global outputs + smem WAR protection
    __syncthreads();

    float acc[2][8][4];
#pragma unroll
    for (int i = 0; i < 2; i++)
#pragma unroll
        for (int j = 0; j < 8; j++)
#pragma unroll
            for (int q = 0; q < 4; q++) acc[i][j][q] = 0.0f;

    auto copyA = [&](int buf, int c) {
#pragma unroll
        for (int i = 0; i < 4; i++) {
            const int idx = i * NTHREADS + tid;    // 0..1023
            const int m   = idx >> 4;              // 0..63
            const int o   = (idx & 15) * 4;        // 0..60
            const int g   = (row0 + m) * DDIM + c * BK + o;
            float* dst = Asm + buf * ABUF + m * ASTRIDE + o;
            if (MODE == MODE_FXV) {
                float4 e4 = ld4(X1 + g);
                float4 v4 = ld4(X2 + g);
                float4 av;
                av.x = e4.x * v4.x * v4.x;
                av.y = e4.y * v4.y * v4.y;
                av.z = e4.z * v4.z * v4.z;
                av.w = e4.w * v4.w * v4.w;
                *(float4*)dst = av;
            } else {
                cp16(dst, A + g);
            }
        }
    };

    copyA(0, 0);
    cp_commit();

#pragma unroll 1
    for (int c = 0; c < 4; c++) {
        if (c < 3) { copyA((c + 1) & 1, c + 1); cp_commit(); cp_wait<1>(); }
        else       { cp_wait<0>(); }
        __syncthreads();

        const float* Ab = Asm + (c & 1) * ABUF;
#pragma unroll 4
        for (int ktl = 0; ktl < 8; ktl++) {
            const int kt = c * 8 + ktl;
            uint32_t bf[8][2];
#pragma unroll
            for (int nt = 0; nt < 8; nt++) {
                const int ntg = warp_n * 8 + nt;
                uint2 v = __ldg((const uint2*)(Wf + ((kt * 32 + ntg) * 32 + lane) * 2));
                bf[nt][0] = v.x; bf[nt][1] = v.y;
            }
            const int kk = ktl * 8 + (lane & 3);
#pragma unroll
            for (int mt = 0; mt < 2; mt++) {
                const int r = warp_m * 32 + mt * 16 + (lane >> 2);
                uint32_t af[4];
                af[0] = __float_as_uint(Ab[r * ASTRIDE + kk]);
                af[1] = __float_as_uint(Ab[(r + 8) * ASTRIDE + kk]);
                af[2] = __float_as_uint(Ab[r * ASTRIDE + kk + 4]);
                af[3] = __float_as_uint(Ab[(r + 8) * ASTRIDE + kk + 4]);
#pragma unroll
                for (int nt = 0; nt < 8; nt++)
                    mma_tf32(acc[mt][nt], af, bf[nt]);
            }
        }
        __syncthreads();
    }

    // ---- fused epilogue ----
#pragma unroll
    for (int mt = 0; mt < 2; mt++) {
#pragma unroll
        for (int nt = 0; nt < 8; nt++) {
            const int r = row0 + warp_m * 32 + mt * 16 + (lane >> 2);
            const int c = warp_n * 64 + nt * 8 + ((lane & 3) << 1);
            const int off0 = r * DDIM + c;
            const int off1 = off0 + 8 * DDIM;
            epi2<MODE>(off0, c, acc[mt][nt][0], acc[mt][nt][1], bias, X1, X2, X3, X4, O1, O2, O3);
            epi2<MODE>(off1, c, acc[mt][nt][2], acc[mt][nt][3], bias, X1, X2, X3, X4, O1, O2, O3);
        }
    }
}

// ---------------- persistent megakernel -------------------------------------
__global__ __launch_bounds__(NTHREADS, 2)
void rhmc_mega(const float* __restrict__ z0, const float* __restrict__ v0,
               const float* __restrict__ bias, float* __restrict__ out)
{
    extern __shared__ float Asm[];
    const int row0 = blockIdx.x * BM;
    const int tid  = threadIdx.x;

    const float* zcur = z0;
    const float* vcur = v0;

    // s, e, r of z0 ; HGR = HG * (r @ W^T)
    gemm_op<MODE_SP, false>(Asm, row0, tid, zcur, bias, 0, 0, 0, 0, gSZ, gE, gR);
    gemm_op<MODE_RW, true >(Asm, row0, tid, gR,   bias, 0, 0, 0, 0, gHGR, 0, 0);

    int cur = -1;
#pragma unroll 1
    for (int l = 0; l < 6; l++) {
        const int a = (cur < 0) ? 0 : (cur + 1) % 3;
        const int b = (cur < 0) ? 1 : (cur + 2) % 3;
        float* ZPa = (a == 0) ? gZP0 : (a == 1) ? gZP1 : gZP2;
        float* ZPb = (b == 0) ? gZP0 : (b == 1) ? gZP1 : gZP2;

        // fx_v: 8 iterations  vh <- vh - HGR + HG*((e*vh^2) @ W^T)
        const float* vh = vcur;
#pragma unroll 1
        for (int i = 0; i < 8; i++) {
            float* vo = (i & 1) ? gVH1 : gVH0;
            gemm_op<MODE_FXV, true>(Asm, row0, tid, 0, bias, gE, vh, vh, gHGR, vo, 0, 0);
            vh = vo;
        }
        // vh == gVH1

        // Gv(vh)
        gemm_op<MODE_GV, false>(Asm, row0, tid, vh, bias, 0, 0, 0, 0, gTMP, 0, 0);
        // BUF, zn_1
        gemm_op<MODE_ZC, true >(Asm, row0, tid, gTMP, bias, zcur, gSZ, vh, 0, gBUF, ZPa, 0);

        // fx_z: 7 more iterations
        const float* zn = ZPa;
#pragma unroll 1
        for (int i = 0; i < 7; i++) {
            float* zo = (i & 1) ? ZPa : ZPb;
            gemm_op<MODE_FXZ, false>(Asm, row0, tid, zn, bias, zn, gBUF, vh, 0, zo, 0, 0);
            zn = zo;
        }
        // zn == ZPb

        // s,e,r,HGR of z_new ; v_new
        gemm_op<MODE_SP, false>(Asm, row0, tid, zn, bias, 0, 0, 0, 0, gSZ, gE, gR);
        gemm_op<MODE_RW, true >(Asm, row0, tid, gR, bias, 0, 0, 0, 0, gHGR, 0, 0);
        gemm_op<MODE_FXV, true>(Asm, row0, tid, 0, bias, gE, vh, vh, gHGR, gV, 0, 0);

        zcur = zn;
        vcur = gV;
        cur  = b;
    }

    // ---- write this CTA's slab to d_out ----
    __syncthreads();
    const int base = row0 * DDIM;
#pragma unroll 1
    for (int i = tid; i < BM * DDIM / 4; i += NTHREADS) {
        ((float4*)(out + base))[i]         = ((const float4*)(zcur + base))[i];
        ((float4*)(out + NELEM + base))[i] = ((const float4*)(vcur + base))[i];
    }
}

// ---------------- host driver ----------------------------------------------
extern "C" void kernel_launch(void* const* d_in, const int* in_sizes, int n_in,
                              void* d_out, int out_size)
{
    const float* z0   = (const float*)d_in[0];
    const float* v0   = (const float*)d_in[1];
    const float* W    = (const float*)d_in[2];
    const float* bias = (const float*)d_in[3];

    cudaFuncSetAttribute(rhmc_mega, cudaFuncAttributeMaxDynamicSharedMemorySize, SMEM_BYTES);

    prep_wfrags<<<256, 256>>>(W);
    rhmc_mega<<<MBATCH / BM, NTHREADS, SMEM_BYTES>>>(z0, v0, bias, (float*)d_out);
}

// round 10
// speedup vs baseline: 1.3814x; 1.1783x over previous
#include <cuda_runtime.h>
#include <math.h>
#include <stdint.h>

#define MBATCH 16384
#define DDIM   256
#define NELEM  (MBATCH * DDIM)

constexpr float HG = 0.005f;   // gamma / 2

constexpr int BM = 64, BN = 256;
constexpr int ASTRIDE = 260;   // 260 % 32 == 4 -> conflict-free direct frag lds
constexpr int SMEM_BYTES = BM * ASTRIDE * (int)sizeof(float);   // 66560
constexpr int NTHREADS = 256;  // 8 warps: 2m x 4n, warp tile 32x64

enum { MODE_SP = 0, MODE_GV = 1, MODE_ZC = 2, MODE_FXZ = 3, MODE_FXV = 4, MODE_RW = 5 };

// ---------------- scratch (static device arrays; no runtime alloc) --------
__device__ float gSZ [NELEM];
__device__ float gE  [NELEM];
__device__ float gR  [NELEM];
__device__ float gHGR[NELEM];
__device__ float gBUF[NELEM];
__device__ float gV  [NELEM];
__device__ float gVH0[NELEM];
__device__ float gVH1[NELEM];
__device__ float gTMP[NELEM];
__device__ float gZP0[NELEM];
__device__ float gZP1[NELEM];
__device__ float gZP2[NELEM];

// Precomputed tf32 W fragments (mma-fragment order), 256KB each.
// idx = ((kt*32 + nt)*32 + lane)*2 + reg ; n = nt*8+(lane>>2), k = kt*8+(lane&3)+4*reg
__device__ uint32_t gWN[65536];   // B[k][n] = W[k][n]   (A @ W)
__device__ uint32_t gWT[65536];   // B[k][n] = W[n][k]   (A @ W^T)

// ---------------- math helpers --------------------------------------------
__device__ __forceinline__ float sp_f(float x) {          // precise softplus
    return fmaxf(x, 0.0f) + log1pf(expf(-fabsf(x)));
}
__device__ __forceinline__ float sp_fast(float x) {       // MUFU softplus
    return fmaxf(x, 0.0f) + __logf(1.0f + __expf(-fabsf(x)));
}
__device__ __forceinline__ float4 ld4(const float* p) { return *(const float4*)p; }

__device__ __forceinline__ uint32_t to_tf32(float f) {
    uint32_t r;
    asm("cvt.rna.tf32.f32 %0, %1;" : "=r"(r) : "f"(f));
    return r;
}
__device__ __forceinline__ void mma_tf32(float c[4], const uint32_t a[4], const uint32_t b[2]) {
    asm volatile(
        "mma.sync.aligned.m16n8k8.row.col.f32.tf32.tf32.f32 "
        "{%0,%1,%2,%3}, {%4,%5,%6,%7}, {%8,%9}, {%0,%1,%2,%3};"
        : "+f"(c[0]), "+f"(c[1]), "+f"(c[2]), "+f"(c[3])
        : "r"(a[0]), "r"(a[1]), "r"(a[2]), "r"(a[3]), "r"(b[0]), "r"(b[1]));
}
__device__ __forceinline__ void cp16(float* smem_dst, const float* gsrc) {
    uint32_t s = (uint32_t)__cvta_generic_to_shared(smem_dst);
    asm volatile("cp.async.cg.shared.global [%0], [%1], 16;" :: "r"(s), "l"(gsrc));
}
__device__ __forceinline__ void cp_commit() { asm volatile("cp.async.commit_group;"); }
template <int N>
__device__ __forceinline__ void cp_wait() { asm volatile("cp.async.wait_group %0;" :: "n"(N)); }

// ---------------- W fragment precompute -------------------------------------
__global__ void prep_wfrags(const float* __restrict__ W) {
    int idx = blockIdx.x * 256 + threadIdx.x;   // 0..65535
    int reg  = idx & 1;
    int lane = (idx >> 1) & 31;
    int nt   = (idx >> 6) & 31;
    int kt   = idx >> 11;
    int n = nt * 8 + (lane >> 2);
    int k = kt * 8 + (lane & 3) + 4 * reg;
    gWN[idx] = to_tf32(W[k * DDIM + n]);
    gWT[idx] = to_tf32(W[n * DDIM + k]);
}

// ---------------- fused epilogue (per float2) -------------------------------
template <int MODE>
__device__ __forceinline__ void epi2(int off, int c, float a0, float a1,
                                     const float* __restrict__ bias,
                                     const float* __restrict__ X1,
                                     const float* __restrict__ X2,
                                     const float* __restrict__ X3,
                                     const float* __restrict__ X4,
                                     float* __restrict__ O1, float* __restrict__ O2,
                                     float* __restrict__ O3)
{
    if (MODE == MODE_SP) {
        float2 b = *(const float2*)(bias + c);
        float s0 = sp_f(a0 + b.x), s1 = sp_f(a1 + b.y);
        float e0 = 0.5f * expm1f(-s0), e1 = 0.5f * expm1f(-s1);
        *(float2*)(O1 + off) = make_float2(s0, s1);
        *(float2*)(O2 + off) = make_float2(e0, e1);
        *(float2*)(O3 + off) = make_float2(__fdividef(e0, s0), __fdividef(e1, s1));
    } else if (MODE == MODE_GV) {
        float2 b = *(const float2*)(bias + c);
        float s0 = sp_f(a0 + b.x), s1 = sp_f(a1 + b.y);
        *(float2*)(O1 + off) = make_float2(__fdividef(0.5f * expm1f(-s0), s0),
                                           __fdividef(0.5f * expm1f(-s1), s1));
    } else if (MODE == MODE_ZC) {
        float2 z = *(const float2*)(X1 + off);
        float2 s = *(const float2*)(X2 + off);
        float2 v = *(const float2*)(X3 + off);
        float svh0 = s.x * v.x, svh1 = s.y * v.y;
        float2 bf = make_float2(HG * (svh0 + 2.0f * a0), HG * (svh1 + 2.0f * a1));
        float2 zn = make_float2(z.x + bf.x + HG * svh0, z.y + bf.y + HG * svh1);
        *(float2*)(O1 + off) = bf;
        *(float2*)(O2 + off) = zn;
    } else if (MODE == MODE_FXZ) {
        float2 b  = *(const float2*)(bias + c);
        float2 zn = *(const float2*)(X1 + off);
        float2 bf = *(const float2*)(X2 + off);
        float2 v  = *(const float2*)(X3 + off);
        float s0 = sp_fast(a0 + b.x), s1 = sp_fast(a1 + b.y);
        *(float2*)(O1 + off) = make_float2(zn.x + bf.x + HG * s0 * v.x,
                                           zn.y + bf.y + HG * s1 * v.y);
    } else if (MODE == MODE_FXV) {
        float2 vb  = *(const float2*)(X3 + off);
        float2 hgr = *(const float2*)(X4 + off);
        *(float2*)(O1 + off) = make_float2(vb.x - hgr.x + HG * a0,
                                           vb.y - hgr.y + HG * a1);
    } else {  // MODE_RW
        *(float2*)(O1 + off) = make_float2(HG * a0, HG * a1);
    }
}

// ---------------- one fused GEMM op (CTA-wide, BM x BN = 64 x 256) ----------
// Single-buffer full-tile staging: 2 barriers per op, barrier-free mainloop.
template <int MODE, bool TRANSB>
__device__ __forceinline__ void gemm_op(
    float* __restrict__ Asm, int row0, int tid,
    const float* __restrict__ A, const float* __restrict__ bias,
    const float* __restrict__ X1, const float* __restrict__ X2,
    const float* __restrict__ X3, const float* __restrict__ X4,
    float* __restrict__ O1, float* __restrict__ O2, float* __restrict__ O3)
{
    const uint32_t* __restrict__ Wf = TRANSB ? gWT : gWN;
    const int lane   = tid & 31;
    const int wid    = tid >> 5;
    const int warp_m = wid >> 2;   // 0..1, 32 rows each
    const int warp_n = wid & 3;    // 0..3, 64 cols each

    // WAR: prior op's mainloop must be done reading smem before we overwrite;
    // also makes prior op's global stores visible to our loads (intra-CTA).
    __syncthreads();

    // ---- stage whole A tile (64 x 256) ----
#pragma unroll
    for (int i = 0; i < 16; i++) {
        const int idx = i * NTHREADS + tid;    // 0..4095
        const int m   = idx >> 6;              // 0..63
        const int o   = (idx & 63) * 4;        // 0..252
        const int g   = (row0 + m) * DDIM + o;
        float* dst = Asm + m * ASTRIDE + o;
        if (MODE == MODE_FXV) {
            float4 e4 = ld4(X1 + g);
            float4 v4 = ld4(X2 + g);
            float4 av;
            av.x = e4.x * v4.x * v4.x;
            av.y = e4.y * v4.y * v4.y;
            av.z = e4.z * v4.z * v4.z;
            av.w = e4.w * v4.w * v4.w;
            *(float4*)dst = av;
        } else {
            cp16(dst, A + g);
        }
    }
    if (MODE != MODE_FXV) { cp_commit(); cp_wait<0>(); }
    __syncthreads();

    float acc[2][8][4];
#pragma unroll
    for (int i = 0; i < 2; i++)
#pragma unroll
        for (int j = 0; j < 8; j++)
#pragma unroll
            for (int q = 0; q < 4; q++) acc[i][j][q] = 0.0f;

    // ---- barrier-free mainloop over all K ----
#pragma unroll 4
    for (int kt = 0; kt < 32; kt++) {
        uint32_t bf[8][2];
#pragma unroll
        for (int nt = 0; nt < 8; nt++) {
            const int ntg = warp_n * 8 + nt;
            uint2 v = __ldg((const uint2*)(Wf + ((kt * 32 + ntg) * 32 + lane) * 2));
            bf[nt][0] = v.x; bf[nt][1] = v.y;
        }
        const int kk = kt * 8 + (lane & 3);
#pragma unroll
        for (int mt = 0; mt < 2; mt++) {
            const int r = warp_m * 32 + mt * 16 + (lane >> 2);
            uint32_t af[4];
            af[0] = __float_as_uint(Asm[r * ASTRIDE + kk]);
            af[1] = __float_as_uint(Asm[(r + 8) * ASTRIDE + kk]);
            af[2] = __float_as_uint(Asm[r * ASTRIDE + kk + 4]);
            af[3] = __float_as_uint(Asm[(r + 8) * ASTRIDE + kk + 4]);
#pragma unroll
            for (int nt = 0; nt < 8; nt++)
                mma_tf32(acc[mt][nt], af, bf[nt]);
        }
    }

    // ---- fused epilogue (global stores; no smem) ----
#pragma unroll
    for (int mt = 0; mt < 2; mt++) {
#pragma unroll
        for (int nt = 0; nt < 8; nt++) {
            const int r = row0 + warp_m * 32 + mt * 16 + (lane >> 2);
            const int c = warp_n * 64 + nt * 8 + ((lane & 3) << 1);
            const int off0 = r * DDIM + c;
            const int off1 = off0 + 8 * DDIM;
            epi2<MODE>(off0, c, acc[mt][nt][0], acc[mt][nt][1], bias, X1, X2, X3, X4, O1, O2, O3);
            epi2<MODE>(off1, c, acc[mt][nt][2], acc[mt][nt][3], bias, X1, X2, X3, X4, O1, O2, O3);
        }
    }
}

// ---------------- persistent megakernel -------------------------------------
__global__ __launch_bounds__(NTHREADS, 2)
void rhmc_mega(const float* __restrict__ z0, const float* __restrict__ v0,
               const float* __restrict__ bias, float* __restrict__ out)
{
    extern __shared__ float Asm[];
    const int row0 = blockIdx.x * BM;
    const int tid  = threadIdx.x;

    const float* zcur = z0;
    const float* vcur = v0;

    // s, e, r of z0 ; HGR = HG * (r @ W^T)
    gemm_op<MODE_SP, false>(Asm, row0, tid, zcur, bias, 0, 0, 0, 0, gSZ, gE, gR);
    gemm_op<MODE_RW, true >(Asm, row0, tid, gR,   bias, 0, 0, 0, 0, gHGR, 0, 0);

    int cur = -1;
#pragma unroll 1
    for (int l = 0; l < 6; l++) {
        const int a = (cur < 0) ? 0 : (cur + 1) % 3;
        const int b = (cur < 0) ? 1 : (cur + 2) % 3;
        float* ZPa = (a == 0) ? gZP0 : (a == 1) ? gZP1 : gZP2;
        float* ZPb = (b == 0) ? gZP0 : (b == 1) ? gZP1 : gZP2;

        // fx_v: 8 iterations  vh <- vh - HGR + HG*((e*vh^2) @ W^T)
        const float* vh = vcur;
#pragma unroll 1
        for (int i = 0; i < 8; i++) {
            float* vo = (i & 1) ? gVH1 : gVH0;
            gemm_op<MODE_FXV, true>(Asm, row0, tid, 0, bias, gE, vh, vh, gHGR, vo, 0, 0);
            vh = vo;
        }
        // vh == gVH1

        // Gv(vh)
        gemm_op<MODE_GV, false>(Asm, row0, tid, vh, bias, 0, 0, 0, 0, gTMP, 0, 0);
        // BUF, zn_1
        gemm_op<MODE_ZC, true >(Asm, row0, tid, gTMP, bias, zcur, gSZ, vh, 0, gBUF, ZPa, 0);

        // fx_z: 7 more iterations
        const float* zn = ZPa;
#pragma unroll 1
        for (int i = 0; i < 7; i++) {
            float* zo = (i & 1) ? ZPa : ZPb;
            gemm_op<MODE_FXZ, false>(Asm, row0, tid, zn, bias, zn, gBUF, vh, 0, zo, 0, 0);
            zn = zo;
        }
        // zn == ZPb

        // s,e,r,HGR of z_new ; v_new
        gemm_op<MODE_SP, false>(Asm, row0, tid, zn, bias, 0, 0, 0, 0, gSZ, gE, gR);
        gemm_op<MODE_RW, true >(Asm, row0, tid, gR, bias, 0, 0, 0, 0, gHGR, 0, 0);
        gemm_op<MODE_FXV, true>(Asm, row0, tid, 0, bias, gE, vh, vh, gHGR, gV, 0, 0);

        zcur = zn;
        vcur = gV;
        cur  = b;
    }

    // ---- write this CTA's slab to d_out ----
    __syncthreads();
    const int base = row0 * DDIM;
#pragma unroll 1
    for (int i = tid; i < BM * DDIM / 4; i += NTHREADS) {
        ((float4*)(out + base))[i]         = ((const float4*)(zcur + base))[i];
        ((float4*)(out + NELEM + base))[i] = ((const float4*)(vcur + base))[i];
    }
}

// ---------------- host driver ----------------------------------------------
extern "C" void kernel_launch(void* const* d_in, const int* in_sizes, int n_in,
                              void* d_out, int out_size)
{
    const float* z0   = (const float*)d_in[0];
    const float* v0   = (const float*)d_in[1];
    const float* W    = (const float*)d_in[2];
    const float* bias = (const float*)d_in[3];

    cudaFuncSetAttribute(rhmc_mega, cudaFuncAttributeMaxDynamicSharedMemorySize, SMEM_BYTES);

    prep_wfrags<<<256, 256>>>(W);
    rhmc_mega<<<MBATCH / BM, NTHREADS, SMEM_BYTES>>>(z0, v0, bias, (float*)d_out);
}

// round 11
// speedup vs baseline: 1.5073x; 1.0911x over previous
#include <cuda_runtime.h>
#include <math.h>
#include <stdint.h>

#define MBATCH 16384
#define DDIM   256
#define NELEM  (MBATCH * DDIM)

constexpr float HG = 0.005f;   // gamma / 2

constexpr int BM = 64, BN = 256;
constexpr int ASTRIDE = 260;   // 260 % 32 == 4 -> conflict-free direct frag lds
constexpr int SMEM_BYTES = BM * ASTRIDE * (int)sizeof(float);   // 66560
constexpr int NTHREADS = 256;  // 8 warps: 2m x 4n, warp tile 32x64

enum { MODE_SP = 0, MODE_GV = 1, MODE_ZC = 2, MODE_FXZ = 3, MODE_FXV = 4, MODE_RW = 5 };

// ---------------- scratch (static device arrays; no runtime alloc) --------
__device__ float gSZ [NELEM];
__device__ float gE  [NELEM];
__device__ float gR  [NELEM];
__device__ float gHGR[NELEM];
__device__ float gBUF[NELEM];
__device__ float gV  [NELEM];
__device__ float gVH0[NELEM];
__device__ float gVH1[NELEM];
__device__ float gTMP[NELEM];
__device__ float gZP0[NELEM];
__device__ float gZP1[NELEM];
__device__ float gZP2[NELEM];

// Precomputed tf32 W fragments (mma-fragment order), 256KB each.
// idx = ((kt*32 + nt)*32 + lane)*2 + reg ; n = nt*8+(lane>>2), k = kt*8+(lane&3)+4*reg
__device__ uint32_t gWN[65536];   // B[k][n] = W[k][n]   (A @ W)
__device__ uint32_t gWT[65536];   // B[k][n] = W[n][k]   (A @ W^T)

// ---------------- math helpers --------------------------------------------
__device__ __forceinline__ float sp_f(float x) {          // precise softplus
    return fmaxf(x, 0.0f) + log1pf(expf(-fabsf(x)));
}
__device__ __forceinline__ float sp_fast(float x) {       // MUFU softplus
    return fmaxf(x, 0.0f) + __logf(1.0f + __expf(-fabsf(x)));
}
__device__ __forceinline__ float4 ld4(const float* p) { return *(const float4*)p; }

__device__ __forceinline__ uint32_t to_tf32(float f) {
    uint32_t r;
    asm("cvt.rna.tf32.f32 %0, %1;" : "=r"(r) : "f"(f));
    return r;
}
__device__ __forceinline__ void mma_tf32(float c[4], const uint32_t a[4], const uint32_t b[2]) {
    asm volatile(
        "mma.sync.aligned.m16n8k8.row.col.f32.tf32.tf32.f32 "
        "{%0,%1,%2,%3}, {%4,%5,%6,%7}, {%8,%9}, {%0,%1,%2,%3};"
        : "+f"(c[0]), "+f"(c[1]), "+f"(c[2]), "+f"(c[3])
        : "r"(a[0]), "r"(a[1]), "r"(a[2]), "r"(a[3]), "r"(b[0]), "r"(b[1]));
}
__device__ __forceinline__ void cp16(float* smem_dst, const float* gsrc) {
    uint32_t s = (uint32_t)__cvta_generic_to_shared(smem_dst);
    asm volatile("cp.async.cg.shared.global [%0], [%1], 16;" :: "r"(s), "l"(gsrc));
}
__device__ __forceinline__ void cp_commit() { asm volatile("cp.async.commit_group;"); }
template <int N>
__device__ __forceinline__ void cp_wait() { asm volatile("cp.async.wait_group %0;" :: "n"(N)); }

// ---------------- W fragment precompute -------------------------------------
__global__ void prep_wfrags(const float* __restrict__ W) {
    int idx = blockIdx.x * 256 + threadIdx.x;   // 0..65535
    int reg  = idx & 1;
    int lane = (idx >> 1) & 31;
    int nt   = (idx >> 6) & 31;
    int kt   = idx >> 11;
    int n = nt * 8 + (lane >> 2);
    int k = kt * 8 + (lane & 3) + 4 * reg;
    gWN[idx] = to_tf32(W[k * DDIM + n]);
    gWT[idx] = to_tf32(W[n * DDIM + k]);
}

// ---------------- fused epilogue (per float2) -------------------------------
template <int MODE>
__device__ __forceinline__ void epi2(int off, int c, float a0, float a1,
                                     const float* __restrict__ bias,
                                     const float* __restrict__ X1,
                                     const float* __restrict__ X2,
                                     const float* __restrict__ X3,
                                     const float* __restrict__ X4,
                                     float* __restrict__ O1, float* __restrict__ O2,
                                     float* __restrict__ O3)
{
    if (MODE == MODE_SP) {
        float2 b = *(const float2*)(bias + c);
        float s0 = sp_f(a0 + b.x), s1 = sp_f(a1 + b.y);
        float e0 = 0.5f * expm1f(-s0), e1 = 0.5f * expm1f(-s1);
        *(float2*)(O1 + off) = make_float2(s0, s1);
        *(float2*)(O2 + off) = make_float2(e0, e1);
        *(float2*)(O3 + off) = make_float2(__fdividef(e0, s0), __fdividef(e1, s1));
    } else if (MODE == MODE_GV) {
        float2 b = *(const float2*)(bias + c);
        float s0 = sp_f(a0 + b.x), s1 = sp_f(a1 + b.y);
        *(float2*)(O1 + off) = make_float2(__fdividef(0.5f * expm1f(-s0), s0),
                                           __fdividef(0.5f * expm1f(-s1), s1));
    } else if (MODE == MODE_ZC) {
        float2 z = *(const float2*)(X1 + off);
        float2 s = *(const float2*)(X2 + off);
        float2 v = *(const float2*)(X3 + off);
        float svh0 = s.x * v.x, svh1 = s.y * v.y;
        float2 bf = make_float2(HG * (svh0 + 2.0f * a0), HG * (svh1 + 2.0f * a1));
        float2 zn = make_float2(z.x + bf.x + HG * svh0, z.y + bf.y + HG * svh1);
        *(float2*)(O1 + off) = bf;
        *(float2*)(O2 + off) = zn;
    } else if (MODE == MODE_FXZ) {
        float2 b  = *(const float2*)(bias + c);
        float2 zn = *(const float2*)(X1 + off);
        float2 bf = *(const float2*)(X2 + off);
        float2 v  = *(const float2*)(X3 + off);
        float s0 = sp_fast(a0 + b.x), s1 = sp_fast(a1 + b.y);
        *(float2*)(O1 + off) = make_float2(zn.x + bf.x + HG * s0 * v.x,
                                           zn.y + bf.y + HG * s1 * v.y);
    } else if (MODE == MODE_FXV) {
        float2 vb  = *(const float2*)(X3 + off);
        float2 hgr = *(const float2*)(X4 + off);
        *(float2*)(O1 + off) = make_float2(vb.x - hgr.x + HG * a0,
                                           vb.y - hgr.y + HG * a1);
    } else {  // MODE_RW
        *(float2*)(O1 + off) = make_float2(HG * a0, HG * a1);
    }
}

// ---------------- one fused GEMM op (CTA-wide, BM x BN = 64 x 256) ----------
// Single-buffer full-tile staging; mainloop barrier-free with software-
// pipelined (register double-buffered) W-fragment loads.
template <int MODE, bool TRANSB>
__device__ __forceinline__ void gemm_op(
    float* __restrict__ Asm, int row0, int tid,
    const float* __restrict__ A, const float* __restrict__ bias,
    const float* __restrict__ X1, const float* __restrict__ X2,
    const float* __restrict__ X3, const float* __restrict__ X4,
    float* __restrict__ O1, float* __restrict__ O2, float* __restrict__ O3)
{
    const uint32_t* __restrict__ Wf = TRANSB ? gWT : gWN;
    const int lane   = tid & 31;
    const int wid    = tid >> 5;
    const int warp_m = wid >> 2;   // 0..1, 32 rows each
    const int warp_n = wid & 3;    // 0..3, 64 cols each

    // WAR: prior op's mainloop must be done reading smem before we overwrite;
    // also makes prior op's global stores visible to our loads (intra-CTA).
    __syncthreads();

    // ---- stage whole A tile (64 x 256) ----
#pragma unroll
    for (int i = 0; i < 16; i++) {
        const int idx = i * NTHREADS + tid;    // 0..4095
        const int m   = idx >> 6;              // 0..63
        const int o   = (idx & 63) * 4;        // 0..252
        const int g   = (row0 + m) * DDIM + o;
        float* dst = Asm + m * ASTRIDE + o;
        if (MODE == MODE_FXV) {
            float4 e4 = ld4(X1 + g);
            float4 v4 = ld4(X2 + g);
            float4 av;
            av.x = e4.x * v4.x * v4.x;
            av.y = e4.y * v4.y * v4.y;
            av.z = e4.z * v4.z * v4.z;
            av.w = e4.w * v4.w * v4.w;
            *(float4*)dst = av;
        } else {
            cp16(dst, A + g);
        }
    }
    if (MODE != MODE_FXV) { cp_commit(); cp_wait<0>(); }
    __syncthreads();

    float acc[2][8][4];
#pragma unroll
    for (int i = 0; i < 2; i++)
#pragma unroll
        for (int j = 0; j < 8; j++)
#pragma unroll
            for (int q = 0; q < 4; q++) acc[i][j][q] = 0.0f;

    // ---- mainloop: register double-buffered bf, barrier-free ----
    const uint32_t* __restrict__ WfBase = Wf + (warp_n * 8) * 64 + lane * 2;

    uint32_t bfp[2][8][2];
#pragma unroll
    for (int nt = 0; nt < 8; nt++) {
        uint2 v = __ldg((const uint2*)(WfBase + nt * 64));
        bfp[0][nt][0] = v.x; bfp[0][nt][1] = v.y;
    }

#pragma unroll 4
    for (int kt = 0; kt < 32; kt++) {
        const int cur = kt & 1, nxt = cur ^ 1;
        if (kt < 31) {
            const uint32_t* p = WfBase + (kt + 1) * 32 * 64;
#pragma unroll
            for (int nt = 0; nt < 8; nt++) {
                uint2 v = __ldg((const uint2*)(p + nt * 64));
                bfp[nxt][nt][0] = v.x; bfp[nxt][nt][1] = v.y;
            }
        }
        const int kk = kt * 8 + (lane & 3);
#pragma unroll
        for (int mt = 0; mt < 2; mt++) {
            const int r = warp_m * 32 + mt * 16 + (lane >> 2);
            uint32_t af[4];
            af[0] = __float_as_uint(Asm[r * ASTRIDE + kk]);
            af[1] = __float_as_uint(Asm[(r + 8) * ASTRIDE + kk]);
            af[2] = __float_as_uint(Asm[r * ASTRIDE + kk + 4]);
            af[3] = __float_as_uint(Asm[(r + 8) * ASTRIDE + kk + 4]);
#pragma unroll
            for (int nt = 0; nt < 8; nt++)
                mma_tf32(acc[mt][nt], af, bfp[cur][nt]);
        }
    }

    // ---- fused epilogue (global stores; no smem) ----
#pragma unroll
    for (int mt = 0; mt < 2; mt++) {
#pragma unroll
        for (int nt = 0; nt < 8; nt++) {
            const int r = row0 + warp_m * 32 + mt * 16 + (lane >> 2);
            const int c = warp_n * 64 + nt * 8 + ((lane & 3) << 1);
            const int off0 = r * DDIM + c;
            const int off1 = off0 + 8 * DDIM;
            epi2<MODE>(off0, c, acc[mt][nt][0], acc[mt][nt][1], bias, X1, X2, X3, X4, O1, O2, O3);
            epi2<MODE>(off1, c, acc[mt][nt][2], acc[mt][nt][3], bias, X1, X2, X3, X4, O1, O2, O3);
        }
    }
}

// ---------------- persistent megakernel -------------------------------------
__global__ __launch_bounds__(NTHREADS, 2)
void rhmc_mega(const float* __restrict__ z0, const float* __restrict__ v0,
               const float* __restrict__ bias, float* __restrict__ out)
{
    extern __shared__ float Asm[];
    const int row0 = blockIdx.x * BM;
    const int tid  = threadIdx.x;

    const float* zcur = z0;
    const float* vcur = v0;

    // s, e, r of z0 ; HGR = HG * (r @ W^T)
    gemm_op<MODE_SP, false>(Asm, row0, tid, zcur, bias, 0, 0, 0, 0, gSZ, gE, gR);
    gemm_op<MODE_RW, true >(Asm, row0, tid, gR,   bias, 0, 0, 0, 0, gHGR, 0, 0);

    int cur = -1;
#pragma unroll 1
    for (int l = 0; l < 6; l++) {
        const int a = (cur < 0) ? 0 : (cur + 1) % 3;
        const int b = (cur < 0) ? 1 : (cur + 2) % 3;
        float* ZPa = (a == 0) ? gZP0 : (a == 1) ? gZP1 : gZP2;
        float* ZPb = (b == 0) ? gZP0 : (b == 1) ? gZP1 : gZP2;

        // fx_v: 8 iterations  vh <- vh - HGR + HG*((e*vh^2) @ W^T)
        const float* vh = vcur;
#pragma unroll 1
        for (int i = 0; i < 8; i++) {
            float* vo = (i & 1) ? gVH1 : gVH0;
            gemm_op<MODE_FXV, true>(Asm, row0, tid, 0, bias, gE, vh, vh, gHGR, vo, 0, 0);
            vh = vo;
        }
        // vh == gVH1

        // Gv(vh)
        gemm_op<MODE_GV, false>(Asm, row0, tid, vh, bias, 0, 0, 0, 0, gTMP, 0, 0);
        // BUF, zn_1
        gemm_op<MODE_ZC, true >(Asm, row0, tid, gTMP, bias, zcur, gSZ, vh, 0, gBUF, ZPa, 0);

        // fx_z: 7 more iterations
        const float* zn = ZPa;
#pragma unroll 1
        for (int i = 0; i < 7; i++) {
            float* zo = (i & 1) ? ZPa : ZPb;
            gemm_op<MODE_FXZ, false>(Asm, row0, tid, zn, bias, zn, gBUF, vh, 0, zo, 0, 0);
            zn = zo;
        }
        // zn == ZPb

        // s,e,r,HGR of z_new ; v_new
        gemm_op<MODE_SP, false>(Asm, row0, tid, zn, bias, 0, 0, 0, 0, gSZ, gE, gR);
        gemm_op<MODE_RW, true >(Asm, row0, tid, gR, bias, 0, 0, 0, 0, gHGR, 0, 0);
        gemm_op<MODE_FXV, true>(Asm, row0, tid, 0, bias, gE, vh, vh, gHGR, gV, 0, 0);

        zcur = zn;
        vcur = gV;
        cur  = b;
    }

    // ---- write this CTA's slab to d_out ----
    __syncthreads();
    const int base = row0 * DDIM;
#pragma unroll 1
    for (int i = tid; i < BM * DDIM / 4; i += NTHREADS) {
        ((float4*)(out + base))[i]         = ((const float4*)(zcur + base))[i];
        ((float4*)(out + NELEM + base))[i] = ((const float4*)(vcur + base))[i];
    }
}

// ---------------- host driver ----------------------------------------------
extern "C" void kernel_launch(void* const* d_in, const int* in_sizes, int n_in,
                              void* d_out, int out_size)
{
    const float* z0   = (const float*)d_in[0];
    const float* v0   = (const float*)d_in[1];
    const float* W    = (const float*)d_in[2];
    const float* bias = (const float*)d_in[3];

    cudaFuncSetAttribute(rhmc_mega, cudaFuncAttributeMaxDynamicSharedMemorySize, SMEM_BYTES);

    prep_wfrags<<<256, 256>>>(W);
    rhmc_mega<<<MBATCH / BM, NTHREADS, SMEM_BYTES>>>(z0, v0, bias, (float*)d_out);
}

// round 13
// speedup vs baseline: 1.8728x; 1.2425x over previous
#include <cuda_runtime.h>
#include <cuda_bf16.h>
#include <math.h>
#include <stdint.h>

#define MBATCH 16384
#define DDIM   256
#define NELEM  (MBATCH * DDIM)

constexpr float HG = 0.005f;   // gamma / 2

constexpr int BM = 64, BN = 256;
constexpr int ASTRIDE_H = 264;  // halves; 528 B row stride; 528%128==16 -> conflict-free
constexpr int ASTRIDE_U = ASTRIDE_H / 2;          // 132 u32 per row
constexpr int SMEM_BYTES = BM * ASTRIDE_H * 2;    // 33792
constexpr int NTHREADS = 256;  // 8 warps: 2m x 4n, warp tile 32x64

enum { MODE_SP = 0, MODE_GV = 1, MODE_ZC = 2, MODE_FXZ = 3, MODE_FXV = 4, MODE_RW = 5 };

// ---------------- scratch (static device arrays; no runtime alloc) --------
__device__ float gSZ [NELEM];
__device__ float gE  [NELEM];
__device__ float gR  [NELEM];
__device__ float gHGR[NELEM];
__device__ float gBUF[NELEM];
__device__ float gV  [NELEM];
__device__ float gVH0[NELEM];
__device__ float gVH1[NELEM];
__device__ float gTMP[NELEM];
__device__ float gZP0[NELEM];
__device__ float gZP1[NELEM];
__device__ float gZP2[NELEM];

// Precomputed bf16 W fragments in m16n8k16 B-fragment order, 128KB each.
// entry idx = ((kt*32 + nt)*32 + lane)*2 + reg   (kt: k/16, nt: n/8)
//   t=lane&3, g=lane>>2, n=nt*8+g, k0=kt*16+2t+(reg?8:0)
//   value = pack_bf16(B[k0][n], B[k0+1][n])
__device__ uint32_t gWN16[32768];   // B[k][n] = W[k][n]   (A @ W)
__device__ uint32_t gWT16[32768];   // B[k][n] = W[n][k]   (A @ W^T)

// ---------------- math helpers --------------------------------------------
__device__ __forceinline__ float sp_f(float x) {          // precise softplus
    return fmaxf(x, 0.0f) + log1pf(expf(-fabsf(x)));
}
__device__ __forceinline__ float sp_fast(float x) {       // MUFU softplus
    return fmaxf(x, 0.0f) + __logf(1.0f + __expf(-fabsf(x)));
}
__device__ __forceinline__ float4 ld4(const float* p) { return *(const float4*)p; }

__device__ __forceinline__ uint32_t pack_bf16(float lo, float hi) {
    __nv_bfloat162 h = __floats2bfloat162_rn(lo, hi);   // .x = lo (low 16 bits)
    return *(uint32_t*)&h;
}

__device__ __forceinline__ void mma_bf16(float c[4], const uint32_t a[4], const uint32_t b[2]) {
    asm volatile(
        "mma.sync.aligned.m16n8k16.row.col.f32.bf16.bf16.f32 "
        "{%0,%1,%2,%3}, {%4,%5,%6,%7}, {%8,%9}, {%0,%1,%2,%3};"
        : "+f"(c[0]), "+f"(c[1]), "+f"(c[2]), "+f"(c[3])
        : "r"(a[0]), "r"(a[1]), "r"(a[2]), "r"(a[3]), "r"(b[0]), "r"(b[1]));
}

// ---------------- W fragment precompute -------------------------------------
__global__ void prep_wfrags(const float* __restrict__ W) {
    int idx = blockIdx.x * 256 + threadIdx.x;   // 0..32767
    int reg  = idx & 1;
    int lane = (idx >> 1) & 31;
    int nt   = (idx >> 6) & 31;
    int kt   = idx >> 11;                       // 0..15
    int t = lane & 3, g = lane >> 2;
    int n  = nt * 8 + g;
    int k0 = kt * 16 + 2 * t + (reg ? 8 : 0);
    gWN16[idx] = pack_bf16(W[k0 * DDIM + n],  W[(k0 + 1) * DDIM + n]);
    gWT16[idx] = pack_bf16(W[n * DDIM + k0],  W[n * DDIM + k0 + 1]);
}

// ---------------- fused epilogue (per float2) -------------------------------
template <int MODE>
__device__ __forceinline__ void epi2(int off, int c, float a0, float a1,
                                     const float* __restrict__ bias,
                                     const float* __restrict__ X1,
                                     const float* __restrict__ X2,
                                     const float* __restrict__ X3,
                                     const float* __restrict__ X4,
                                     float* __restrict__ O1, float* __restrict__ O2,
                                     float* __restrict__ O3)
{
    if (MODE == MODE_SP) {
        float2 b = *(const float2*)(bias + c);
        float s0 = sp_f(a0 + b.x), s1 = sp_f(a1 + b.y);
        float e0 = 0.5f * expm1f(-s0), e1 = 0.5f * expm1f(-s1);
        *(float2*)(O1 + off) = make_float2(s0, s1);
        *(float2*)(O2 + off) = make_float2(e0, e1);
        *(float2*)(O3 + off) = make_float2(__fdividef(e0, s0), __fdividef(e1, s1));
    } else if (MODE == MODE_GV) {
        float2 b = *(const float2*)(bias + c);
        float s0 = sp_f(a0 + b.x), s1 = sp_f(a1 + b.y);
        *(float2*)(O1 + off) = make_float2(__fdividef(0.5f * expm1f(-s0), s0),
                                           __fdividef(0.5f * expm1f(-s1), s1));
    } else if (MODE == MODE_ZC) {
        float2 z = *(const float2*)(X1 + off);
        float2 s = *(const float2*)(X2 + off);
        float2 v = *(const float2*)(X3 + off);
        float svh0 = s.x * v.x, svh1 = s.y * v.y;
        float2 bf = make_float2(HG * (svh0 + 2.0f * a0), HG * (svh1 + 2.0f * a1));
        float2 zn = make_float2(z.x + bf.x + HG * svh0, z.y + bf.y + HG * svh1);
        *(float2*)(O1 + off) = bf;
        *(float2*)(O2 + off) = zn;
    } else if (MODE == MODE_FXZ) {
        float2 b  = *(const float2*)(bias + c);
        float2 zn = *(const float2*)(X1 + off);
        float2 bf = *(const float2*)(X2 + off);
        float2 v  = *(const float2*)(X3 + off);
        float s0 = sp_fast(a0 + b.x), s1 = sp_fast(a1 + b.y);
        *(float2*)(O1 + off) = make_float2(zn.x + bf.x + HG * s0 * v.x,
                                           zn.y + bf.y + HG * s1 * v.y);
    } else if (MODE == MODE_FXV) {
        float2 vb  = *(const float2*)(X3 + off);
        float2 hgr = *(const float2*)(X4 + off);
        *(float2*)(O1 + off) = make_float2(vb.x - hgr.x + HG * a0,
                                           vb.y - hgr.y + HG * a1);
    } else {  // MODE_RW
        *(float2*)(O1 + off) = make_float2(HG * a0, HG * a1);
    }
}

// ---------------- one fused GEMM op (CTA-wide, BM x BN = 64 x 256) ----------
// bf16 m16n8k16; A tile staged as row-major bf16 (stride 264 halves);
// barrier-free mainloop with register double-buffered W fragments.
template <int MODE, bool TRANSB>
__device__ __forceinline__ void gemm_op(
    uint32_t* __restrict__ Asm, int row0, int tid,
    const float* __restrict__ A, const float* __restrict__ bias,
    const float* __restrict__ X1, const float* __restrict__ X2,
    const float* __restrict__ X3, const float* __restrict__ X4,
    float* __restrict__ O1, float* __restrict__ O2, float* __restrict__ O3)
{
    const uint32_t* __restrict__ Wf = TRANSB ? gWT16 : gWN16;
    const int lane   = tid & 31;
    const int wid    = tid >> 5;
    const int warp_m = wid >> 2;   // 0..1, 32 rows each
    const int warp_n = wid & 3;    // 0..3, 64 cols each

    // WAR: prior op's mainloop must finish reading smem; also orders prior
    // op's global stores before our loads (intra-CTA).
    __syncthreads();

    // ---- stage whole A tile (64 x 256) as bf16 ----
#pragma unroll
    for (int i = 0; i < 16; i++) {
        const int idx = i * NTHREADS + tid;    // 0..4095
        const int m   = idx >> 6;              // 0..63
        const int o4  = idx & 63;              // float4 index in row
        const int g   = (row0 + m) * DDIM + o4 * 4;
        float4 av;
        if (MODE == MODE_FXV) {
            float4 e4 = ld4(X1 + g);
            float4 v4 = ld4(X2 + g);
            av.x = e4.x * v4.x * v4.x;
            av.y = e4.y * v4.y * v4.y;
            av.z = e4.z * v4.z * v4.z;
            av.w = e4.w * v4.w * v4.w;
        } else {
            av = ld4(A + g);
        }
        uint2 p;
        p.x = pack_bf16(av.x, av.y);
        p.y = pack_bf16(av.z, av.w);
        ((uint2*)Asm)[m * (ASTRIDE_U / 2) + o4] = p;
    }
    __syncthreads();

    float acc[2][8][4];
#pragma unroll
    for (int i = 0; i < 2; i++)
#pragma unroll
        for (int j = 0; j < 8; j++)
#pragma unroll
            for (int q = 0; q < 4; q++) acc[i][j][q] = 0.0f;

    // ---- mainloop: 16 k-chunks of 16; reg double-buffered bf ----
    const uint32_t* __restrict__ WfBase = Wf + ((warp_n * 8) * 32 + lane) * 2;
    const int t = lane & 3, gg = lane >> 2;

    uint32_t bfp[2][8][2];
#pragma unroll
    for (int nt = 0; nt < 8; nt++) {
        uint2 v = __ldg((const uint2*)(WfBase + nt * 64));
        bfp[0][nt][0] = v.x; bfp[0][nt][1] = v.y;
    }

#pragma unroll 4
    for (int kt = 0; kt < 16; kt++) {
        const int cur = kt & 1, nxt = cur ^ 1;
        if (kt < 15) {
            const uint32_t* p = WfBase + (kt + 1) * 32 * 64;
#pragma unroll
            for (int nt = 0; nt < 8; nt++) {
                uint2 v = __ldg((const uint2*)(p + nt * 64));
                bfp[nxt][nt][0] = v.x; bfp[nxt][nt][1] = v.y;
            }
        }
        const int ku = kt * 8 + t;             // u32 col index of (k=kt*16+2t)
#pragma unroll
        for (int mt = 0; mt < 2; mt++) {
            const int r = warp_m * 32 + mt * 16 + gg;
            uint32_t af[4];
            af[0] = Asm[r * ASTRIDE_U + ku];
            af[1] = Asm[(r + 8) * ASTRIDE_U + ku];
            af[2] = Asm[r * ASTRIDE_U + ku + 4];
            af[3] = Asm[(r + 8) * ASTRIDE_U + ku + 4];
#pragma unroll
            for (int nt = 0; nt < 8; nt++)
                mma_bf16(acc[mt][nt], af, bfp[cur][nt]);
        }
    }

    // ---- fused epilogue (global stores; no smem) ----
#pragma unroll
    for (int mt = 0; mt < 2; mt++) {
#pragma unroll
        for (int nt = 0; nt < 8; nt++) {
            const int r = row0 + warp_m * 32 + mt * 16 + gg;
            const int c = warp_n * 64 + nt * 8 + (t << 1);
            const int off0 = r * DDIM + c;
            const int off1 = off0 + 8 * DDIM;
            epi2<MODE>(off0, c, acc[mt][nt][0], acc[mt][nt][1], bias, X1, X2, X3, X4, O1, O2, O3);
            epi2<MODE>(off1, c, acc[mt][nt][2], acc[mt][nt][3], bias, X1, X2, X3, X4, O1, O2, O3);
        }
    }
}

// ---------------- persistent megakernel -------------------------------------
__global__ __launch_bounds__(NTHREADS, 2)
void rhmc_mega(const float* __restrict__ z0, const float* __restrict__ v0,
               const float* __restrict__ bias, float* __restrict__ out)
{
    extern __shared__ uint32_t Asm[];
    const int row0 = blockIdx.x * BM;
    const int tid  = threadIdx.x;

    const float* zcur = z0;
    const float* vcur = v0;

    // s, e, r of z0 ; HGR = HG * (r @ W^T)
    gemm_op<MODE_SP, false>(Asm, row0, tid, zcur, bias, 0, 0, 0, 0, gSZ, gE, gR);
    gemm_op<MODE_RW, true >(Asm, row0, tid, gR,   bias, 0, 0, 0, 0, gHGR, 0, 0);

    int cur = -1;
#pragma unroll 1
    for (int l = 0; l < 6; l++) {
        const int a = (cur < 0) ? 0 : (cur + 1) % 3;
        const int b = (cur < 0) ? 1 : (cur + 2) % 3;
        float* ZPa = (a == 0) ? gZP0 : (a == 1) ? gZP1 : gZP2;
        float* ZPb = (b == 0) ? gZP0 : (b == 1) ? gZP1 : gZP2;

        // fx_v: 8 iterations  vh <- vh - HGR + HG*((e*vh^2) @ W^T)
        const float* vh = vcur;
#pragma unroll 1
        for (int i = 0; i < 8; i++) {
            float* vo = (i & 1) ? gVH1 : gVH0;
            gemm_op<MODE_FXV, true>(Asm, row0, tid, 0, bias, gE, vh, vh, gHGR, vo, 0, 0);
            vh = vo;
        }
        // vh == gVH1

        // Gv(vh)
        gemm_op<MODE_GV, false>(Asm, row0, tid, vh, bias, 0, 0, 0, 0, gTMP, 0, 0);
        // BUF, zn_1
        gemm_op<MODE_ZC, true >(Asm, row0, tid, gTMP, bias, zcur, gSZ, vh, 0, gBUF, ZPa, 0);

        // fx_z: 7 more iterations
        const float* zn = ZPa;
#pragma unroll 1
        for (int i = 0; i < 7; i++) {
            float* zo = (i & 1) ? ZPa : ZPb;
            gemm_op<MODE_FXZ, false>(Asm, row0, tid, zn, bias, zn, gBUF, vh, 0, zo, 0, 0);
            zn = zo;
        }
        // zn == ZPb

        // s,e,r,HGR of z_new ; v_new
        gemm_op<MODE_SP, false>(Asm, row0, tid, zn, bias, 0, 0, 0, 0, gSZ, gE, gR);
        gemm_op<MODE_RW, true >(Asm, row0, tid, gR, bias, 0, 0, 0, 0, gHGR, 0, 0);
        gemm_op<MODE_FXV, true>(Asm, row0, tid, 0, bias, gE, vh, vh, gHGR, gV, 0, 0);

        zcur = zn;
        vcur = gV;
        cur  = b;
    }

    // ---- write this CTA's slab to d_out ----
    __syncthreads();
    const int base = row0 * DDIM;
#pragma unroll 1
    for (int i = tid; i < BM * DDIM / 4; i += NTHREADS) {
        ((float4*)(out + base))[i]         = ((const float4*)(zcur + base))[i];
        ((float4*)(out + NELEM + base))[i] = ((const float4*)(vcur + base))[i];
    }
}

// ---------------- host driver ----------------------------------------------
extern "C" void kernel_launch(void* const* d_in, const int* in_sizes, int n_in,
                              void* d_out, int out_size)
{
    const float* z0   = (const float*)d_in[0];
    const float* v0   = (const float*)d_in[1];
    const float* W    = (const float*)d_in[2];
    const float* bias = (const float*)d_in[3];

    cudaFuncSetAttribute(rhmc_mega, cudaFuncAttributeMaxDynamicSharedMemorySize, SMEM_BYTES);

    prep_wfrags<<<128, 256>>>(W);
    rhmc_mega<<<MBATCH / BM, NTHREADS, SMEM_BYTES>>>(z0, v0, bias, (float*)d_out);
}

// round 16
// speedup vs baseline: 2.7630x; 1.4753x over previous
#include <cuda_runtime.h>
#include <cuda_bf16.h>
#include <math.h>
#include <stdint.h>

#define MBATCH 16384
#define DDIM   256
#define NELEM  (MBATCH * DDIM)

constexpr float HG = 0.005f;   // gamma / 2

constexpr int BM = 64, BN = 256;
constexpr int ASTRIDE_H = 264;  // halves; 528 B row stride; 528%128==16 -> conflict-free
constexpr int ASTRIDE_U = ASTRIDE_H / 2;          // 132 u32 per row
constexpr int SMEM_BYTES = BM * ASTRIDE_H * 2;    // 33792
constexpr int NTHREADS = 256;  // 8 warps: 2m x 4n, warp tile 32x64

// Modes:
// SP4 : s=sp(acc+b); O1=s, O2=e=.5expm1(-s), O3=r=e/s, O4=u=acc+b
// GV  : O1 = .5 expm1(-s)/s, s=sp(acc+b)
// ZC2 : O1 = BUF = HG(SZ*vh + 2acc); O2 = D = 2HG(SZ*vh + acc)   (X1=SZ, X2=vh)
// FXZ8: delta=acc; sum = SZ + sum_{n=1..7} sp(U + n*delta);
//       O1 = z + 8*BUF + HG*vh*sum                     (X1=U, X2=SZ, X3=BUF, X4=vh, X5=z)
// FXV : A = E*vh^2 on-fly; O1 = vh - HGR + HG*acc      (X1=E, X2=vh, X3=vh, X4=HGR)
// RW  : O1 = HG*acc
// FXG : A = E*v^2 on-fly;  O1 = HGR - HG*acc  (= hg)   (X1=E, X2=v, X4=HGR)
// FXS : A = E*(8v^2-56*v*hg+140*hg^2) on-fly; O1 = v - 8*HGR + HG*acc
//                                                      (X1=E, X2=v, X3=hg, X4=HGR)
enum { MODE_SP4 = 0, MODE_GV = 1, MODE_ZC2 = 2, MODE_FXZ8 = 3, MODE_FXV = 4,
       MODE_RW = 5, MODE_FXG = 6, MODE_FXS = 7 };

// ---------------- scratch (static device arrays; no runtime alloc) --------
__device__ float gSZ [NELEM];
__device__ float gE  [NELEM];
__device__ float gR  [NELEM];
__device__ float gU  [NELEM];
__device__ float gHGR[NELEM];
__device__ float gHGq[NELEM];
__device__ float gBUF[NELEM];
__device__ float gD  [NELEM];
__device__ float gTMP[NELEM];
__device__ float gVH [NELEM];
__device__ float gV  [NELEM];
__device__ float gZP0[NELEM];
__device__ float gZP1[NELEM];

// Precomputed bf16 W fragments in m16n8k16 B-fragment order, 128KB each.
__device__ uint32_t gWN16[32768];   // B[k][n] = W[k][n]   (A @ W)
__device__ uint32_t gWT16[32768];   // B[k][n] = W[n][k]   (A @ W^T)

// ---------------- math helpers --------------------------------------------
__device__ __forceinline__ float sp_f(float x) {          // precise softplus
    return fmaxf(x, 0.0f) + log1pf(expf(-fabsf(x)));
}
__device__ __forceinline__ float sp_fast(float x) {       // MUFU softplus
    return fmaxf(x, 0.0f) + __logf(1.0f + __expf(-fabsf(x)));
}
__device__ __forceinline__ float4 ld4(const float* p) { return *(const float4*)p; }

__device__ __forceinline__ uint32_t pack_bf16(float lo, float hi) {
    __nv_bfloat162 h = __floats2bfloat162_rn(lo, hi);
    return *(uint32_t*)&h;
}
__device__ __forceinline__ void mma_bf16(float c[4], const uint32_t a[4], const uint32_t b[2]) {
    asm volatile(
        "mma.sync.aligned.m16n8k16.row.col.f32.bf16.bf16.f32 "
        "{%0,%1,%2,%3}, {%4,%5,%6,%7}, {%8,%9}, {%0,%1,%2,%3};"
        : "+f"(c[0]), "+f"(c[1]), "+f"(c[2]), "+f"(c[3])
        : "r"(a[0]), "r"(a[1]), "r"(a[2]), "r"(a[3]), "r"(b[0]), "r"(b[1]));
}

// ---------------- W fragment precompute -------------------------------------
__global__ void prep_wfrags(const float* __restrict__ W) {
    int idx = blockIdx.x * 256 + threadIdx.x;   // 0..32767
    int reg  = idx & 1;
    int lane = (idx >> 1) & 31;
    int nt   = (idx >> 6) & 31;
    int kt   = idx >> 11;                       // 0..15
    int t = lane & 3, g = lane >> 2;
    int n  = nt * 8 + g;
    int k0 = kt * 16 + 2 * t + (reg ? 8 : 0);
    gWN16[idx] = pack_bf16(W[k0 * DDIM + n],  W[(k0 + 1) * DDIM + n]);
    gWT16[idx] = pack_bf16(W[n * DDIM + k0],  W[n * DDIM + k0 + 1]);
}

// ---------------- fused epilogue (per float2) -------------------------------
template <int MODE>
__device__ __forceinline__ void epi2(int off, int c, float a0, float a1,
                                     const float* __restrict__ bias,
                                     const float* __restrict__ X1,
                                     const float* __restrict__ X2,
                                     const float* __restrict__ X3,
                                     const float* __restrict__ X4,
                                     const float* __restrict__ X5,
                                     float* __restrict__ O1, float* __restrict__ O2,
                                     float* __restrict__ O3, float* __restrict__ O4)
{
    if (MODE == MODE_SP4) {
        float2 b = *(const float2*)(bias + c);
        float u0 = a0 + b.x, u1 = a1 + b.y;
        float s0 = sp_f(u0), s1 = sp_f(u1);
        float e0 = 0.5f * expm1f(-s0), e1 = 0.5f * expm1f(-s1);
        *(float2*)(O1 + off) = make_float2(s0, s1);
        *(float2*)(O2 + off) = make_float2(e0, e1);
        *(float2*)(O3 + off) = make_float2(__fdividef(e0, s0), __fdividef(e1, s1));
        *(float2*)(O4 + off) = make_float2(u0, u1);
    } else if (MODE == MODE_GV) {
        float2 b = *(const float2*)(bias + c);
        float s0 = sp_f(a0 + b.x), s1 = sp_f(a1 + b.y);
        *(float2*)(O1 + off) = make_float2(__fdividef(0.5f * expm1f(-s0), s0),
                                           __fdividef(0.5f * expm1f(-s1), s1));
    } else if (MODE == MODE_ZC2) {
        float2 s = *(const float2*)(X1 + off);
        float2 v = *(const float2*)(X2 + off);
        float svh0 = s.x * v.x, svh1 = s.y * v.y;
        *(float2*)(O1 + off) = make_float2(HG * (svh0 + 2.0f * a0),
                                           HG * (svh1 + 2.0f * a1));
        *(float2*)(O2 + off) = make_float2(2.0f * HG * (svh0 + a0),
                                           2.0f * HG * (svh1 + a1));
    } else if (MODE == MODE_FXZ8) {
        float2 u  = *(const float2*)(X1 + off);
        float2 sz = *(const float2*)(X2 + off);
        float2 bf = *(const float2*)(X3 + off);
        float2 vh = *(const float2*)(X4 + off);
        float2 z  = *(const float2*)(X5 + off);
        float sum0 = sz.x, sum1 = sz.y;
#pragma unroll
        for (int n = 1; n < 8; n++) {
            sum0 += sp_fast(u.x + (float)n * a0);
            sum1 += sp_fast(u.y + (float)n * a1);
        }
        *(float2*)(O1 + off) = make_float2(z.x + 8.0f * bf.x + HG * vh.x * sum0,
                                           z.y + 8.0f * bf.y + HG * vh.y * sum1);
    } else if (MODE == MODE_FXV) {
        float2 vb  = *(const float2*)(X3 + off);
        float2 hgr = *(const float2*)(X4 + off);
        *(float2*)(O1 + off) = make_float2(vb.x - hgr.x + HG * a0,
                                           vb.y - hgr.y + HG * a1);
    } else if (MODE == MODE_RW) {
        *(float2*)(O1 + off) = make_float2(HG * a0, HG * a1);
    } else if (MODE == MODE_FXG) {
        float2 hgr = *(const float2*)(X4 + off);
        *(float2*)(O1 + off) = make_float2(hgr.x - HG * a0, hgr.y - HG * a1);
    } else {  // MODE_FXS
        float2 v   = *(const float2*)(X2 + off);
        float2 hgr = *(const float2*)(X4 + off);
        *(float2*)(O1 + off) = make_float2(v.x - 8.0f * hgr.x + HG * a0,
                                           v.y - 8.0f * hgr.y + HG * a1);
    }
}

// ---------------- one fused GEMM op (CTA-wide, BM x BN = 64 x 256) ----------
// bf16 m16n8k16; A tile staged as row-major bf16 (stride 264 halves);
// barrier-free mainloop with register double-buffered W fragments.
template <int MODE, bool TRANSB>
__device__ __forceinline__ void gemm_op(
    uint32_t* __restrict__ Asm, int row0, int tid,
    const float* __restrict__ A, const float* __restrict__ bias,
    const float* __restrict__ X1, const float* __restrict__ X2,
    const float* __restrict__ X3, const float* __restrict__ X4,
    const float* __restrict__ X5,
    float* __restrict__ O1, float* __restrict__ O2,
    float* __restrict__ O3, float* __restrict__ O4)
{
    const uint32_t* __restrict__ Wf = TRANSB ? gWT16 : gWN16;
    const int lane   = tid & 31;
    const int wid    = tid >> 5;
    const int warp_m = wid >> 2;   // 0..1, 32 rows each
    const int warp_n = wid & 3;    // 0..3, 64 cols each

    // WAR + RAW ordering between consecutive ops (intra-CTA).
    __syncthreads();

    // ---- stage whole A tile (64 x 256) as bf16 ----
#pragma unroll
    for (int i = 0; i < 16; i++) {
        const int idx = i * NTHREADS + tid;    // 0..4095
        const int m   = idx >> 6;              // 0..63
        const int o4  = idx & 63;              // float4 index in row
        const int g   = (row0 + m) * DDIM + o4 * 4;
        float4 av;
        if (MODE == MODE_FXV || MODE == MODE_FXG) {
            float4 e4 = ld4(X1 + g);
            float4 v4 = ld4(X2 + g);
            av.x = e4.x * v4.x * v4.x;
            av.y = e4.y * v4.y * v4.y;
            av.z = e4.z * v4.z * v4.z;
            av.w = e4.w * v4.w * v4.w;
        } else if (MODE == MODE_FXS) {
            float4 e4 = ld4(X1 + g);
            float4 v4 = ld4(X2 + g);
            float4 h4 = ld4(X3 + g);
            av.x = e4.x * (8.0f * v4.x * v4.x - 56.0f * v4.x * h4.x + 140.0f * h4.x * h4.x);
            av.y = e4.y * (8.0f * v4.y * v4.y - 56.0f * v4.y * h4.y + 140.0f * h4.y * h4.y);
            av.z = e4.z * (8.0f * v4.z * v4.z - 56.0f * v4.z * h4.z + 140.0f * h4.z * h4.z);
            av.w = e4.w * (8.0f * v4.w * v4.w - 56.0f * v4.w * h4.w + 140.0f * h4.w * h4.w);
        } else {
            av = ld4(A + g);
        }
        uint2 p;
        p.x = pack_bf16(av.x, av.y);
        p.y = pack_bf16(av.z, av.w);
        ((uint2*)Asm)[m * (ASTRIDE_U / 2) + o4] = p;
    }
    __syncthreads();

    float acc[2][8][4];
#pragma unroll
    for (int i = 0; i < 2; i++)
#pragma unroll
        for (int j = 0; j < 8; j++)
#pragma unroll
            for (int q = 0; q < 4; q++) acc[i][j][q] = 0.0f;

    // ---- mainloop: 16 k-chunks of 16; reg double-buffered bf ----
    const uint32_t* __restrict__ WfBase = Wf + ((warp_n * 8) * 32 + lane) * 2;
    const int t = lane & 3, gg = lane >> 2;

    uint32_t bfp[2][8][2];
#pragma unroll
    for (int nt = 0; nt < 8; nt++) {
        uint2 v = __ldg((const uint2*)(WfBase + nt * 64));
        bfp[0][nt][0] = v.x; bfp[0][nt][1] = v.y;
    }

#pragma unroll 4
    for (int kt = 0; kt < 16; kt++) {
        const int cur = kt & 1, nxt = cur ^ 1;
        if (kt < 15) {
            const uint32_t* p = WfBase + (kt + 1) * 32 * 64;
#pragma unroll
            for (int nt = 0; nt < 8; nt++) {
                uint2 v = __ldg((const uint2*)(p + nt * 64));
                bfp[nxt][nt][0] = v.x; bfp[nxt][nt][1] = v.y;
            }
        }
        const int ku = kt * 8 + t;             // u32 col index of (k=kt*16+2t)
#pragma unroll
        for (int mt = 0; mt < 2; mt++) {
            const int r = warp_m * 32 + mt * 16 + gg;
            uint32_t af[4];
            af[0] = Asm[r * ASTRIDE_U + ku];
            af[1] = Asm[(r + 8) * ASTRIDE_U + ku];
            af[2] = Asm[r * ASTRIDE_U + ku + 4];
            af[3] = Asm[(r + 8) * ASTRIDE_U + ku + 4];
#pragma unroll
            for (int nt = 0; nt < 8; nt++)
                mma_bf16(acc[mt][nt], af, bfp[cur][nt]);
        }
    }

    // ---- fused epilogue (global stores; no smem) ----
#pragma unroll
    for (int mt = 0; mt < 2; mt++) {
#pragma unroll
        for (int nt = 0; nt < 8; nt++) {
            const int r = row0 + warp_m * 32 + mt * 16 + gg;
            const int c = warp_n * 64 + nt * 8 + (t << 1);
            const int off0 = r * DDIM + c;
            const int off1 = off0 + 8 * DDIM;
            epi2<MODE>(off0, c, acc[mt][nt][0], acc[mt][nt][1], bias, X1, X2, X3, X4, X5, O1, O2, O3, O4);
            epi2<MODE>(off1, c, acc[mt][nt][2], acc[mt][nt][3], bias, X1, X2, X3, X4, X5, O1, O2, O3, O4);
        }
    }
}

// ---------------- persistent megakernel -------------------------------------
__global__ __launch_bounds__(NTHREADS, 2)
void rhmc_mega(const float* __restrict__ z0, const float* __restrict__ v0,
               const float* __restrict__ bias, float* __restrict__ out)
{
    extern __shared__ uint32_t Asm[];
    const int row0 = blockIdx.x * BM;
    const int tid  = threadIdx.x;

    const float* zcur = z0;
    const float* vcur = v0;

    // s, e, r, u of z0 ; HGR = HG * (r @ W^T)
    gemm_op<MODE_SP4, false>(Asm, row0, tid, zcur, bias, 0, 0, 0, 0, 0, gSZ, gE, gR, gU);
    gemm_op<MODE_RW,  true >(Asm, row0, tid, gR,   bias, 0, 0, 0, 0, 0, gHGR, 0, 0, 0);

#pragma unroll 1
    for (int l = 0; l < 6; l++) {
        float* ZPn = (l & 1) ? gZP1 : gZP0;

        // ---- fx_v closed form (2 GEMMs) ----
        // hg = HG * dHdz(z, v) = HGR - HG*((e*v^2) @ W^T)
        gemm_op<MODE_FXG, true>(Asm, row0, tid, 0, bias, gE, vcur, 0, gHGR, 0, gHGq, 0, 0, 0);
        // vh = v - 8*HGR + HG*((e*(8v^2-56*v*hg+140*hg^2)) @ W^T)
        gemm_op<MODE_FXS, true>(Asm, row0, tid, 0, bias, gE, vcur, gHGq, gHGR, 0, gVH, 0, 0, 0);

        // ---- Gv(vh) ----
        gemm_op<MODE_GV, false>(Asm, row0, tid, gVH, bias, 0, 0, 0, 0, 0, gTMP, 0, 0, 0);
        // ---- C = Gv@W^T ; BUF = HG(s_z*vh + 2C); D = BUF + HG*s_z*vh ----
        gemm_op<MODE_ZC2, true>(Asm, row0, tid, gTMP, bias, gSZ, gVH, 0, 0, 0, gBUF, gD, 0, 0);

        // ---- fx_z closed form (1 GEMM): delta = D@W ; zn = z + 8BUF + HG*vh*sum ----
        gemm_op<MODE_FXZ8, false>(Asm, row0, tid, gD, bias, gU, gSZ, gBUF, gVH, zcur, ZPn, 0, 0, 0);

        // ---- s,e,r,u of z_new ; HGR_new ----
        gemm_op<MODE_SP4, false>(Asm, row0, tid, ZPn, bias, 0, 0, 0, 0, 0, gSZ, gE, gR, gU);
        gemm_op<MODE_RW,  true >(Asm, row0, tid, gR,  bias, 0, 0, 0, 0, 0, gHGR, 0, 0, 0);

        // ---- v_new = vh - HGR_new + HG*((e_new*vh^2) @ W^T) ----
        gemm_op<MODE_FXV, true>(Asm, row0, tid, 0, bias, gE, gVH, gVH, gHGR, 0, gV, 0, 0, 0);

        zcur = ZPn;
        vcur = gV;
    }

    // ---- write this CTA's slab to d_out ----
    __syncthreads();
    const int base = row0 * DDIM;
#pragma unroll 1
    for (int i = tid; i < BM * DDIM / 4; i += NTHREADS) {
        ((float4*)(out + base))[i]         = ((const float4*)(zcur + base))[i];
        ((float4*)(out + NELEM + base))[i] = ((const float4*)(vcur + base))[i];
    }
}

// ---------------- host driver ----------------------------------------------
extern "C" void kernel_launch(void* const* d_in, const int* in_sizes, int n_in,
                              void* d_out, int out_size)
{
    const float* z0   = (const float*)d_in[0];
    const float* v0   = (const float*)d_in[1];
    const float* W    = (const float*)d_in[2];
    const float* bias = (const float*)d_in[3];

    cudaFuncSetAttribute(rhmc_mega, cudaFuncAttributeMaxDynamicSharedMemorySize, SMEM_BYTES);

    prep_wfrags<<<128, 256>>>(W);
    rhmc_mega<<<MBATCH / BM, NTHREADS, SMEM_BYTES>>>(z0, v0, bias, (float*)d_out);
}